// round 14
// baseline (speedup 1.0000x reference)
#include <cuda_runtime.h>
#include <math.h>

#define IMG    256
#define PSZ    16
#define PAD    8
#define NBR    64
#define CH     3
#define INV2S2 12.5f
#define EPSV   1e-7f
#define PADP   20      // patchT row pitch [c][q][p]
#define PFX    28      // FxT row pitch   [q][wl]
#define PFY    24      // FyT row pitch   [p][hl]
#define PT     28      // tT row pitch    [c][p][wl]
#define NBRUSH 2048
#define SLOTS  4
#define GRID   (NBRUSH / SLOTS)   // 512

// dynamic smem layout (floats)
#define SZ_PATCH (CH * PSZ * PADP)   // 960
#define SZ_FX    (PSZ * PFX)         // 448
#define SZ_FY    (PSZ * PFY)         // 384
#define SZ_TT    (CH * PSZ * PT)     // 1344
#define OFF_FX   (SLOTS * SZ_PATCH)
#define OFF_FY   (OFF_FX + SLOTS * SZ_FX)
#define OFF_TT   (OFF_FY + SLOTS * SZ_FY)
#define DYN_FLOATS (OFF_TT + SLOTS * SZ_TT)     // 12544 -> 50176 B

__global__ void zero_out_kernel(float4* __restrict__ out, int n4) {
    const int base = blockIdx.x * 384 + threadIdx.x;
    #pragma unroll
    for (int i = 0; i < 3; i++) {
        const int idx = base + i * 128;
        if (idx < n4) out[idx] = make_float4(0.f, 0.f, 0.f, 0.f);
    }
}

__global__ __launch_bounds__(256) void brush_scatter_kernel(
    const float* __restrict__ brushes,   // [B, N, 2]
    const float* __restrict__ patches,   // [B, N, 3, 16, 16]
    float* __restrict__ out)             // [B, 3, 256, 256]
{
    extern __shared__ __align__(16) float dyn_s[];
    float* patchT_s = dyn_s;                 // [slot][960]
    float* FxT_s    = dyn_s + OFF_FX;        // [slot][448]
    float* FyT_s    = dyn_s + OFF_FY;        // [slot][384]
    float* tT_s     = dyn_s + OFF_TT;        // [slot][1344]

    __shared__ float e_s[SLOTS][2][8];
    __shared__ float rden_s[SLOTS][2][16];
    __shared__ int   t0_s[SLOTS][2];
    __shared__ int   w0_s[SLOTS][2];

    const int bn0 = blockIdx.x * SLOTS;
    const int b   = bn0 >> 6;
    const int tid = threadIdx.x;

    // ---- phase A: warps 0-1 exp tables + denoms; warps 2-7 patch loads ----
    if (tid < 64) {
        const int slot = tid >> 4;
        const int ax   = (tid >> 3) & 1;
        const int k    = tid & 7;
        const float g  = brushes[(bn0 + slot) * 2 + ax] * (float)IMG;
        const int  fl  = (int)floorf(g);
        const int  t0  = fl - 10;
        const float d  = (float)(t0 + k) - (g - 7.5f);
        e_s[slot][ax][k] = __expf(-d * d * INV2S2);
        if (k == 0) {
            t0_s[slot][ax] = t0;
            w0_s[slot][ax] = (ax == 0) ? ((fl - 11) & ~3) : (fl - 11);
        }
        __syncwarp();
        #pragma unroll
        for (int h = 0; h < 2; h++) {
            const int q = k + h * 8;
            int klo = -PAD - q - t0;            if (klo < 0) klo = 0;
            int khi = (IMG + PAD - 1) - q - t0; if (khi > 7) khi = 7;
            float s = 0.f;
            #pragma unroll
            for (int kk = 0; kk < 8; kk++)
                if (kk >= klo && kk <= khi) s += e_s[slot][ax][kk];
            s += EPSV;
            rden_s[slot][ax][q] = (ax == 0) ? 1.f / (s * (float)NBR) : 1.f / s;
        }
    } else {
        const float* pbase = patches + (size_t)bn0 * (CH * PSZ * PSZ);
        const int t = tid - 64;
        #pragma unroll
        for (int it = 0; it < 16; it++) {
            const int i = t + it * 192;          // 3072 elems total
            const int slot = i / 768;
            const int r = i - slot * 768;
            const int c = r >> 8;
            const int p = (r >> 4) & 15;
            const int q = r & 15;
            patchT_s[slot * SZ_PATCH + (c * PSZ + q) * PADP + p] = pbase[i];
        }
    }
    __syncthreads();

    // ---- phase B: fill FxT[q][wl] + FyT[p][hl] via lookups (4*832 entries) ----
    #pragma unroll
    for (int it = 0; it < 13; it++) {
        const int i = tid + it * 256;
        if (i >= SLOTS * 832) break;
        const int slot = i / 832;
        const int r    = i - slot * 832;
        if (r < PSZ * PFX) {
            const int q  = r / PFX;
            const int wl = r - q * PFX;
            const int w  = w0_s[slot][0] + wl;
            const int idx = w - q - t0_s[slot][0];
            float val = 0.f;
            if (w >= 0 && w < IMG && (unsigned)idx < 8u)
                val = e_s[slot][0][idx] * rden_s[slot][0][q];
            FxT_s[slot * SZ_FX + r] = val;
        } else {
            const int rr = r - PSZ * PFX;
            const int p  = rr / PFY;
            const int hl = rr - p * PFY;
            const int h  = w0_s[slot][1] + hl;
            const int idx = h - p - t0_s[slot][1];
            float val = 0.f;
            if (h >= 0 && h < IMG && (unsigned)idx < 8u)
                val = e_s[slot][1][idx] * rden_s[slot][1][p];
            FyT_s[slot * SZ_FY + rr] = val;
        }
    }
    __syncthreads();

    // ---- stage 1: tT[c][p][wl] = sum_q FxT[q][wl] * patchT[c][q][p] ----
    // task = (slot, c, pg{0,1}, wlq{0..6}): 168 tasks, 8p x 4wl block
    if (tid < SLOTS * 42) {
        const int wlq = tid % 7;
        int u = tid / 7;
        const int pg = u & 1;  u >>= 1;
        const int c  = u % 3;
        const int slot = u / 3;
        const int p0  = pg * 8;
        const int wl0 = wlq * 4;
        const float* fxb = FxT_s + slot * SZ_FX;
        const float* ptb = patchT_s + slot * SZ_PATCH;

        float acc[4][8] = {};   // [wl][p]
        #pragma unroll
        for (int q = 0; q < PSZ; q++) {
            const float4 fx  = *(const float4*)&fxb[q * PFX + wl0];
            const float4 pv0 = *(const float4*)&ptb[(c * PSZ + q) * PADP + p0];
            const float4 pv1 = *(const float4*)&ptb[(c * PSZ + q) * PADP + p0 + 4];
            const float fxa[4] = {fx.x, fx.y, fx.z, fx.w};
            const float pva[8] = {pv0.x, pv0.y, pv0.z, pv0.w,
                                  pv1.x, pv1.y, pv1.z, pv1.w};
            #pragma unroll
            for (int i = 0; i < 4; i++)
                #pragma unroll
                for (int pp = 0; pp < 8; pp++)
                    acc[i][pp] = fmaf(fxa[i], pva[pp], acc[i][pp]);
        }
        float* ttb = tT_s + slot * SZ_TT;
        #pragma unroll
        for (int pp = 0; pp < 8; pp++) {
            float4 o = make_float4(acc[0][pp], acc[1][pp], acc[2][pp], acc[3][pp]);
            *(float4*)&ttb[(c * PSZ + p0 + pp) * PT + wl0] = o;
        }
    }
    __syncthreads();

    // ---- stage 2: task = (slot, c, hg{0,1,2}, wlq{0..6}): 252 tasks, 8h x 4w ----
    if (tid < SLOTS * 63) {
        const int wlq = tid % 7;
        int u = tid / 7;
        const int hg = u % 3;  u /= 3;
        const int c  = u % 3;
        const int slot = u / 3;
        const int wl0 = wlq * 4;
        const int hl0 = hg * 8;
        const float* ttb = tT_s + slot * SZ_TT;
        const float* fyb = FyT_s + slot * SZ_FY;

        float acc[8][4] = {};   // [hl][wl]
        #pragma unroll
        for (int p = 0; p < PSZ; p++) {
            const float4 tv  = *(const float4*)&ttb[(c * PSZ + p) * PT + wl0];
            const float4 fy0 = *(const float4*)&fyb[p * PFY + hl0];
            const float4 fy1 = *(const float4*)&fyb[p * PFY + hl0 + 4];
            const float fya[8] = {fy0.x, fy0.y, fy0.z, fy0.w,
                                  fy1.x, fy1.y, fy1.z, fy1.w};
            const float tva[4] = {tv.x, tv.y, tv.z, tv.w};
            #pragma unroll
            for (int i = 0; i < 8; i++)
                #pragma unroll
                for (int k = 0; k < 4; k++)
                    acc[i][k] = fmaf(fya[i], tva[k], acc[i][k]);
        }

        const int wb = w0_s[slot][0] + wl0;
        const int hb = w0_s[slot][1] + hl0;
        float* base = out + ((size_t)b * CH + c) * (IMG * IMG);
        const bool wok = (wb >= 0) && (wb + 3 < IMG);
        #pragma unroll
        for (int i = 0; i < 8; i++) {
            const int h = hb + i;
            if (h < 0 || h >= IMG) continue;
            float* row = base + (size_t)h * IMG;
            if (wok) {
                asm volatile("red.global.add.v4.f32 [%0], {%1, %2, %3, %4};"
                             :: "l"(row + wb), "f"(acc[i][0]), "f"(acc[i][1]),
                                "f"(acc[i][2]), "f"(acc[i][3])
                             : "memory");
            } else {
                #pragma unroll
                for (int k = 0; k < 4; k++) {
                    const int w = wb + k;
                    if (w >= 0 && w < IMG) atomicAdd(row + w, acc[i][k]);
                }
            }
        }
    }
}

extern "C" void kernel_launch(void* const* d_in, const int* in_sizes, int n_in,
                              void* d_out, int out_size) {
    const float* brushes = (const float*)d_in[0];   // [32,64,2]
    const float* patches = (const float*)d_in[1];   // [32,64,3,16,16]
    float* out = (float*)d_out;                     // [32,3,256,256]

    static bool attr_set = false;
    if (!attr_set) {
        cudaFuncSetAttribute(brush_scatter_kernel,
                             cudaFuncAttributeMaxDynamicSharedMemorySize,
                             DYN_FLOATS * (int)sizeof(float));
        attr_set = true;
    }

    const int n4 = out_size / 4;
    zero_out_kernel<<<(n4 + 383) / 384, 128>>>((float4*)out, n4);
    brush_scatter_kernel<<<GRID, 256, DYN_FLOATS * sizeof(float)>>>(
        brushes, patches, out);
}

// round 15
// speedup vs baseline: 1.1218x; 1.1218x over previous
#include <cuda_runtime.h>
#include <math.h>

#define IMG    256
#define PSZ    16
#define PAD    8
#define NBR    64
#define CH     3
#define INV2S2 12.5f
#define EPSV   1e-7f
#define PADP   20      // patchT row pitch [c][q][p]
#define PFX    28      // FxT row pitch   [q][wl]
#define PFY    24      // FyT row pitch   [p][hl]
#define PT     28      // tT row pitch    [c][p][wl]
#define NBRUSH 2048
#define SLOTS  2
#define GRID   (NBRUSH / SLOTS)   // 1024
#define NTHR   128

// dynamic smem layout (floats)
#define SZ_PATCH (CH * PSZ * PADP)   // 960
#define SZ_FX    (PSZ * PFX)         // 448
#define SZ_FY    (PSZ * PFY)         // 384
#define SZ_TT    (CH * PSZ * PT)     // 1344
#define OFF_FX   (SLOTS * SZ_PATCH)
#define OFF_FY   (OFF_FX + SLOTS * SZ_FX)
#define OFF_TT   (OFF_FY + SLOTS * SZ_FY)
#define DYN_FLOATS (OFF_TT + SLOTS * SZ_TT)     // 6272 -> 25088 B

__global__ void zero_out_kernel(float4* __restrict__ out, int n4) {
    const int base = blockIdx.x * 384 + threadIdx.x;
    #pragma unroll
    for (int i = 0; i < 3; i++) {
        const int idx = base + i * 128;
        if (idx < n4) out[idx] = make_float4(0.f, 0.f, 0.f, 0.f);
    }
}

__global__ __launch_bounds__(NTHR) void brush_scatter_kernel(
    const float* __restrict__ brushes,   // [B, N, 2]
    const float* __restrict__ patches,   // [B, N, 3, 16, 16]
    float* __restrict__ out)             // [B, 3, 256, 256]
{
    extern __shared__ __align__(16) float dyn_s[];
    float* patchT_s = dyn_s;                 // [slot][960]
    float* FxT_s    = dyn_s + OFF_FX;        // [slot][448]
    float* FyT_s    = dyn_s + OFF_FY;        // [slot][384]
    float* tT_s     = dyn_s + OFF_TT;        // [slot][1344]

    __shared__ float e_s[SLOTS][2][8];
    __shared__ float rden_s[SLOTS][2][16];
    __shared__ int   t0_s[SLOTS][2];
    __shared__ int   w0_s[SLOTS][2];

    const int bn0 = blockIdx.x * SLOTS;
    const int b   = bn0 >> 6;
    const int tid = threadIdx.x;

    // ---- phase A: warp 0 exp tables + denoms (both slots); warps 1-3 patch loads ----
    if (tid < 32) {
        const int slot = (tid >> 4) & 1;
        const int ax   = (tid >> 3) & 1;
        const int k    = tid & 7;
        const float g  = brushes[(bn0 + slot) * 2 + ax] * (float)IMG;
        const int  fl  = (int)floorf(g);
        const int  t0  = fl - 10;
        const float d  = (float)(t0 + k) - (g - 7.5f);
        e_s[slot][ax][k] = __expf(-d * d * INV2S2);
        if (k == 0) {
            t0_s[slot][ax] = t0;
            w0_s[slot][ax] = (ax == 0) ? ((fl - 11) & ~3) : (fl - 11);
        }
        __syncwarp();
        #pragma unroll
        for (int h = 0; h < 2; h++) {
            const int q = k + h * 8;
            int klo = -PAD - q - t0;            if (klo < 0) klo = 0;
            int khi = (IMG + PAD - 1) - q - t0; if (khi > 7) khi = 7;
            float s = 0.f;
            #pragma unroll
            for (int kk = 0; kk < 8; kk++)
                if (kk >= klo && kk <= khi) s += e_s[slot][ax][kk];
            s += EPSV;
            rden_s[slot][ax][q] = (ax == 0) ? 1.f / (s * (float)NBR) : 1.f / s;
        }
    } else {
        const float* pbase = patches + (size_t)bn0 * (CH * PSZ * PSZ);
        const int t = tid - 32;
        #pragma unroll
        for (int it = 0; it < 16; it++) {
            const int i = t + it * 96;           // 1536 elems total
            const int slot = i >= 768;
            const int r = i - slot * 768;
            const int c = r >> 8;
            const int p = (r >> 4) & 15;
            const int q = r & 15;
            patchT_s[slot * SZ_PATCH + (c * PSZ + q) * PADP + p] = pbase[i];
        }
    }
    __syncthreads();

    // ---- phase B: fill FxT[q][wl] + FyT[p][hl] via lookups (2*832 entries) ----
    #pragma unroll
    for (int it = 0; it < 13; it++) {
        const int i = tid + it * NTHR;
        if (i >= SLOTS * 832) break;
        const int slot = i >= 832;
        const int r    = i - slot * 832;
        if (r < PSZ * PFX) {
            const int q  = r / PFX;
            const int wl = r - q * PFX;
            const int w  = w0_s[slot][0] + wl;
            const int idx = w - q - t0_s[slot][0];
            float val = 0.f;
            if (w >= 0 && w < IMG && (unsigned)idx < 8u)
                val = e_s[slot][0][idx] * rden_s[slot][0][q];
            FxT_s[slot * SZ_FX + r] = val;
        } else {
            const int rr = r - PSZ * PFX;
            const int p  = rr / PFY;
            const int hl = rr - p * PFY;
            const int h  = w0_s[slot][1] + hl;
            const int idx = h - p - t0_s[slot][1];
            float val = 0.f;
            if (h >= 0 && h < IMG && (unsigned)idx < 8u)
                val = e_s[slot][1][idx] * rden_s[slot][1][p];
            FyT_s[slot * SZ_FY + rr] = val;
        }
    }
    __syncthreads();

    // ---- stage 1: tT[c][p][wl] = sum_q FxT[q][wl] * patchT[c][q][p] ----
    // task = (slot, c, pg{0,1}, wlq{0..6}): 84 tasks, 8p x 4wl block
    if (tid < SLOTS * 42) {
        const int wlq = tid % 7;
        int u = tid / 7;
        const int pg = u & 1;  u >>= 1;
        const int c  = u % 3;
        const int slot = u / 3;
        const int p0  = pg * 8;
        const int wl0 = wlq * 4;
        const float* fxb = FxT_s + slot * SZ_FX;
        const float* ptb = patchT_s + slot * SZ_PATCH;

        float acc[4][8] = {};   // [wl][p]
        #pragma unroll
        for (int q = 0; q < PSZ; q++) {
            const float4 fx  = *(const float4*)&fxb[q * PFX + wl0];
            const float4 pv0 = *(const float4*)&ptb[(c * PSZ + q) * PADP + p0];
            const float4 pv1 = *(const float4*)&ptb[(c * PSZ + q) * PADP + p0 + 4];
            const float fxa[4] = {fx.x, fx.y, fx.z, fx.w};
            const float pva[8] = {pv0.x, pv0.y, pv0.z, pv0.w,
                                  pv1.x, pv1.y, pv1.z, pv1.w};
            #pragma unroll
            for (int i = 0; i < 4; i++)
                #pragma unroll
                for (int pp = 0; pp < 8; pp++)
                    acc[i][pp] = fmaf(fxa[i], pva[pp], acc[i][pp]);
        }
        float* ttb = tT_s + slot * SZ_TT;
        #pragma unroll
        for (int pp = 0; pp < 8; pp++) {
            float4 o = make_float4(acc[0][pp], acc[1][pp], acc[2][pp], acc[3][pp]);
            *(float4*)&ttb[(c * PSZ + p0 + pp) * PT + wl0] = o;
        }
    }
    __syncthreads();

    // ---- stage 2: task = (slot, c, hg{0,1,2}, wlq{0..6}): 126 tasks, 8h x 4w ----
    if (tid < SLOTS * 63) {
        const int wlq = tid % 7;
        int u = tid / 7;
        const int hg = u % 3;  u /= 3;
        const int c  = u % 3;
        const int slot = u / 3;
        const int wl0 = wlq * 4;
        const int hl0 = hg * 8;
        const float* ttb = tT_s + slot * SZ_TT;
        const float* fyb = FyT_s + slot * SZ_FY;

        float acc[8][4] = {};   // [hl][wl]
        #pragma unroll
        for (int p = 0; p < PSZ; p++) {
            const float4 tv  = *(const float4*)&ttb[(c * PSZ + p) * PT + wl0];
            const float4 fy0 = *(const float4*)&fyb[p * PFY + hl0];
            const float4 fy1 = *(const float4*)&fyb[p * PFY + hl0 + 4];
            const float fya[8] = {fy0.x, fy0.y, fy0.z, fy0.w,
                                  fy1.x, fy1.y, fy1.z, fy1.w};
            const float tva[4] = {tv.x, tv.y, tv.z, tv.w};
            #pragma unroll
            for (int i = 0; i < 8; i++)
                #pragma unroll
                for (int k = 0; k < 4; k++)
                    acc[i][k] = fmaf(fya[i], tva[k], acc[i][k]);
        }

        const int wb = w0_s[slot][0] + wl0;
        const int hb = w0_s[slot][1] + hl0;
        float* base = out + ((size_t)b * CH + c) * (IMG * IMG);
        const bool wok = (wb >= 0) && (wb + 3 < IMG);
        #pragma unroll
        for (int i = 0; i < 8; i++) {
            const int h = hb + i;
            if (h < 0 || h >= IMG) continue;
            float* row = base + (size_t)h * IMG;
            if (wok) {
                asm volatile("red.global.add.v4.f32 [%0], {%1, %2, %3, %4};"
                             :: "l"(row + wb), "f"(acc[i][0]), "f"(acc[i][1]),
                                "f"(acc[i][2]), "f"(acc[i][3])
                             : "memory");
            } else {
                #pragma unroll
                for (int k = 0; k < 4; k++) {
                    const int w = wb + k;
                    if (w >= 0 && w < IMG) atomicAdd(row + w, acc[i][k]);
                }
            }
        }
    }
}

extern "C" void kernel_launch(void* const* d_in, const int* in_sizes, int n_in,
                              void* d_out, int out_size) {
    const float* brushes = (const float*)d_in[0];   // [32,64,2]
    const float* patches = (const float*)d_in[1];   // [32,64,3,16,16]
    float* out = (float*)d_out;                     // [32,3,256,256]

    const int n4 = out_size / 4;
    zero_out_kernel<<<(n4 + 383) / 384, 128>>>((float4*)out, n4);
    brush_scatter_kernel<<<GRID, NTHR, DYN_FLOATS * sizeof(float)>>>(
        brushes, patches, out);
}